// round 5
// baseline (speedup 1.0000x reference)
#include <cuda_runtime.h>
#include <cuda_bf16.h>
#include <cstdint>
#include <cstddef>

// ---------------------------------------------------------------------------
// Problem constants
// ---------------------------------------------------------------------------
#define B_DIM  8192
#define IN_DIM 2048
#define H_DIM  2048
#define KTOT   (IN_DIM + H_DIM)   // 4096

// Output layout (flattened tuple order):
//   new_h[B,H] | concat[B,4096] | pre_gate[B,H] | gate[B,H] | values[B,H] | pre_h[B,H]
static constexpr size_t OFF_NH  = 0;
static constexpr size_t OFF_CAT = (size_t)B_DIM * H_DIM;
static constexpr size_t OFF_PG  = OFF_CAT + (size_t)B_DIM * KTOT;
static constexpr size_t OFF_GT  = OFF_PG + (size_t)B_DIM * H_DIM;
static constexpr size_t OFF_VL  = OFF_GT + (size_t)B_DIM * H_DIM;
static constexpr size_t OFF_PH  = OFF_VL + (size_t)B_DIM * H_DIM;

// ---------------------------------------------------------------------------
// bf16 scratch (static device arrays — allocation-free)
// Gate GEMM uses single-rounded bf16 (bias-dominated output tolerates it).
// Values GEMM uses hi/lo split (3-term compensated product).
// ---------------------------------------------------------------------------
__device__ __align__(128) __nv_bfloat16 g_in_hi[(size_t)B_DIM * IN_DIM];
__device__ __align__(128) __nv_bfloat16 g_in_lo[(size_t)B_DIM * IN_DIM];
__device__ __align__(128) __nv_bfloat16 g_st_hi[(size_t)B_DIM * H_DIM];
__device__ __align__(128) __nv_bfloat16 g_wg_hi[(size_t)H_DIM * KTOT];
__device__ __align__(128) __nv_bfloat16 g_wi_hi[(size_t)H_DIM * IN_DIM];
__device__ __align__(128) __nv_bfloat16 g_wi_lo[(size_t)H_DIM * IN_DIM];

// ---------------------------------------------------------------------------
// Small PTX helpers (all baseline PTX — compiles for plain sm_103 target)
// ---------------------------------------------------------------------------
__device__ __forceinline__ uint32_t smem_to_u32(const void* p) {
    uint32_t a;
    asm("{ .reg .u64 t; cvta.to.shared.u64 t, %1; cvt.u32.u64 %0, t; }"
        : "=r"(a) : "l"(p));
    return a;
}

__device__ __forceinline__ void cp_async16(uint32_t dst, const void* src) {
    asm volatile("cp.async.cg.shared.global [%0], [%1], 16;\n"
                 :: "r"(dst), "l"(src));
}
#define CP_COMMIT() asm volatile("cp.async.commit_group;\n" ::: "memory")
#define CP_WAIT(n)  asm volatile("cp.async.wait_group %0;\n" :: "n"(n) : "memory")

__device__ __forceinline__ void ldsm_x4(uint32_t* r, uint32_t addr) {
    asm volatile("ldmatrix.sync.aligned.m8n8.x4.shared.b16 {%0,%1,%2,%3}, [%4];"
                 : "=r"(r[0]), "=r"(r[1]), "=r"(r[2]), "=r"(r[3]) : "r"(addr));
}

__device__ __forceinline__ void mma16816(float* c, const uint32_t* a,
                                         uint32_t b0, uint32_t b1) {
    asm volatile(
        "mma.sync.aligned.m16n8k16.row.col.f32.bf16.bf16.f32 "
        "{%0,%1,%2,%3}, {%4,%5,%6,%7}, {%8,%9}, {%0,%1,%2,%3};"
        : "+f"(c[0]), "+f"(c[1]), "+f"(c[2]), "+f"(c[3])
        : "r"(a[0]), "r"(a[1]), "r"(a[2]), "r"(a[3]), "r"(b0), "r"(b1));
}

// ---------------------------------------------------------------------------
// Pass 1: fp32 -> bf16 (hi [, lo]) split + optional concat output
// which: 0 = input (hi+lo, concat left), 1 = state (hi, concat right),
//        2 = gate_weights (hi), 3 = weights_i (hi+lo)
// ---------------------------------------------------------------------------
__global__ void cvt_kernel(const float4* __restrict__ src, int n4, int which,
                           int off4, float4* __restrict__ cdst) {
    __nv_bfloat162* hi;
    __nv_bfloat162* lo = nullptr;
    if (which == 0)      { hi = (__nv_bfloat162*)g_in_hi; lo = (__nv_bfloat162*)g_in_lo; }
    else if (which == 1) { hi = (__nv_bfloat162*)g_st_hi; }
    else if (which == 2) { hi = (__nv_bfloat162*)g_wg_hi; }
    else                 { hi = (__nv_bfloat162*)g_wi_hi; lo = (__nv_bfloat162*)g_wi_lo; }

    for (int i = blockIdx.x * blockDim.x + threadIdx.x; i < n4;
         i += gridDim.x * blockDim.x) {
        float4 v = src[i];
        __nv_bfloat16 h0 = __float2bfloat16_rn(v.x);
        __nv_bfloat16 h1 = __float2bfloat16_rn(v.y);
        __nv_bfloat16 h2 = __float2bfloat16_rn(v.z);
        __nv_bfloat16 h3 = __float2bfloat16_rn(v.w);
        __nv_bfloat162 hp0; hp0.x = h0; hp0.y = h1;
        __nv_bfloat162 hp1; hp1.x = h2; hp1.y = h3;
        hi[2 * i]     = hp0;
        hi[2 * i + 1] = hp1;
        if (lo) {
            __nv_bfloat162 lp0, lp1;
            lp0.x = __float2bfloat16_rn(v.x - __bfloat162float(h0));
            lp0.y = __float2bfloat16_rn(v.y - __bfloat162float(h1));
            lp1.x = __float2bfloat16_rn(v.z - __bfloat162float(h2));
            lp1.y = __float2bfloat16_rn(v.w - __bfloat162float(h3));
            lo[2 * i]     = lp0;
            lo[2 * i + 1] = lp1;
        }
        if (cdst) {
            int b = i >> 9;           // 512 float4 per source row
            int c = i & 511;
            cdst[(b << 10) + off4 + c] = v;
        }
    }
}

// ---------------------------------------------------------------------------
// Multi-segment bf16 TN GEMM (A [M,K] row-major, B [N,K] row-major)
//   C[M,N] = sum_seg A_seg @ B_seg^T   (fp32 accumulate via mma.sync HMMA)
// CTA tile 128x128, 256 threads, warp tile 64x32, K-chunk 32, 4-stage cp.async.
// mode 0: pre_gate/gate epilogue (add bias, clip).  mode 1: values (tanh).
// ---------------------------------------------------------------------------
static constexpr int STAGES = 4;
static constexpr int STAGE_BYTES = 16384;         // A 8KB + B 8KB
static constexpr int GEMM_SMEM = STAGES * STAGE_BYTES;  // 64 KB

__device__ __forceinline__ void load_stage(uint32_t sbase, int stage,
                                           const __nv_bfloat16* A,
                                           const __nv_bfloat16* Bp,
                                           int kc, int astride, int bstride,
                                           int tid) {
    uint32_t sA = sbase + stage * STAGE_BYTES;
    uint32_t sB = sA + 8192;
#pragma unroll
    for (int h = 0; h < 2; h++) {
        int id = tid + h * 256;       // 0..511
        int r  = id >> 2;             // row 0..127
        int c4 = id & 3;              // 16B chunk within 64B row
        uint32_t sw = (uint32_t)((c4 ^ ((r >> 1) & 3)) << 4);
        cp_async16(sA + r * 64 + sw, A + (size_t)r * astride + kc + c4 * 8);
        cp_async16(sB + r * 64 + sw, Bp + (size_t)r * bstride + kc + c4 * 8);
    }
}

__global__ void __launch_bounds__(256, 2)
gemm_kernel(const __nv_bfloat16* __restrict__ a0,
            const __nv_bfloat16* __restrict__ a1,
            const __nv_bfloat16* __restrict__ a2,
            const __nv_bfloat16* __restrict__ b0,
            const __nv_bfloat16* __restrict__ b1,
            const __nv_bfloat16* __restrict__ b2,
            int astride, int bstride, int nseg,
            const float* __restrict__ bias,
            float* __restrict__ out, int mode) {
    extern __shared__ char smem[];
    uint32_t sbase = smem_to_u32(smem);
    const int tid  = threadIdx.x;
    const int lane = tid & 31;
    const int wid  = tid >> 5;
    const int wm   = wid & 1;         // 2 warps over M
    const int wn   = wid >> 1;        // 4 warps over N

    // consecutive blocks share the M strip -> A reuse in L2
    const int nt = blockIdx.x & 15;
    const int mt = blockIdx.x >> 4;
    const int row0 = mt * 128;
    const int col0 = nt * 128;

    const __nv_bfloat16* As[3] = { a0 + (size_t)row0 * astride,
                                   a1 + (size_t)row0 * astride,
                                   a2 + (size_t)row0 * astride };
    const __nv_bfloat16* Bs[3] = { b0 + (size_t)col0 * bstride,
                                   b1 + (size_t)col0 * bstride,
                                   b2 + (size_t)col0 * bstride };

    float acc[4][4][4];               // [mfrag][n-octet][quad]
#pragma unroll
    for (int i = 0; i < 4; i++)
#pragma unroll
        for (int j = 0; j < 4; j++)
#pragma unroll
            for (int q = 0; q < 4; q++) acc[i][j][q] = 0.0f;

    const int chunks_per_seg = IN_DIM / 32;       // 64
    const int total = nseg * chunks_per_seg;

    // prologue: stages 0..STAGES-2
#pragma unroll
    for (int ci = 0; ci < STAGES - 1; ci++) {
        load_stage(sbase, ci, As[ci >> 6], Bs[ci >> 6], (ci & 63) * 32,
                   astride, bstride, tid);
        CP_COMMIT();
    }

    for (int ci = 0; ci < total; ci++) {
        CP_WAIT(STAGES - 2);
        __syncthreads();

        int nci = ci + STAGES - 1;
        if (nci < total) {
            load_stage(sbase, nci & (STAGES - 1), As[nci >> 6], Bs[nci >> 6],
                       (nci & 63) * 32, astride, bstride, tid);
        }
        CP_COMMIT();

        uint32_t sA = sbase + (ci & (STAGES - 1)) * STAGE_BYTES;
        uint32_t sB = sA + 8192;
#pragma unroll
        for (int ks = 0; ks < 2; ks++) {
            int chunk = ks * 2 + (lane >> 4);
            uint32_t afr[4][4];
#pragma unroll
            for (int mf = 0; mf < 4; mf++) {
                int r = wm * 64 + mf * 16 + (lane & 15);
                uint32_t addr = sA + r * 64 + ((chunk ^ ((r >> 1) & 3)) << 4);
                ldsm_x4(afr[mf], addr);
            }
            uint32_t bfr[2][4];
#pragma unroll
            for (int nf = 0; nf < 2; nf++) {
                int r = wn * 32 + nf * 16 + (lane & 15);
                uint32_t addr = sB + r * 64 + ((chunk ^ ((r >> 1) & 3)) << 4);
                ldsm_x4(bfr[nf], addr);
            }
#pragma unroll
            for (int mf = 0; mf < 4; mf++)
#pragma unroll
                for (int no = 0; no < 4; no++) {
                    uint32_t bb0 = bfr[no >> 1][no & 1];
                    uint32_t bb1 = bfr[no >> 1][(no & 1) + 2];
                    mma16816(acc[mf][no], afr[mf], bb0, bb1);
                }
        }
    }

    // ---- Epilogue ----
    const int r_in = lane >> 2;
    const int c_in = (lane & 3) * 2;
#pragma unroll
    for (int mf = 0; mf < 4; mf++) {
#pragma unroll
        for (int no = 0; no < 4; no++) {
            int r = row0 + wm * 64 + mf * 16 + r_in;
            int c = col0 + wn * 32 + no * 8 + c_in;
            float* q = acc[mf][no];
#pragma unroll
            for (int half = 0; half < 2; half++) {
                int rr = r + half * 8;
                float d0 = q[half * 2 + 0];
                float d1 = q[half * 2 + 1];
                size_t o = (size_t)rr * H_DIM + c;
                if (mode == 0) {
                    float pg0 = d0 + bias[c];
                    float pg1 = d1 + bias[c + 1];
                    float g0 = fminf(fmaxf(pg0, 0.0f), 1.0f);
                    float g1 = fminf(fmaxf(pg1, 0.0f), 1.0f);
                    *reinterpret_cast<float2*>(out + OFF_PG + o) = make_float2(pg0, pg1);
                    *reinterpret_cast<float2*>(out + OFF_GT + o) = make_float2(g0, g1);
                } else {
                    float v0 = tanhf(d0);
                    float v1 = tanhf(d1);
                    *reinterpret_cast<float2*>(out + OFF_VL + o) = make_float2(v0, v1);
                }
            }
        }
    }
}

// ---------------------------------------------------------------------------
// Blend: pre_h = state*(1-g) + values*g ; new_h = relu(pre_h)
// ---------------------------------------------------------------------------
__global__ void blend_kernel(const float4* __restrict__ state,
                             float* __restrict__ out) {
    const float4* gt = (const float4*)(out + OFF_GT);
    const float4* vl = (const float4*)(out + OFF_VL);
    float4* ph = (float4*)(out + OFF_PH);
    float4* nh = (float4*)(out + OFF_NH);
    int n4 = B_DIM * H_DIM / 4;
    for (int i = blockIdx.x * blockDim.x + threadIdx.x; i < n4;
         i += gridDim.x * blockDim.x) {
        float4 g = gt[i];
        float4 v = vl[i];
        float4 s = state[i];
        float4 p, h;
        p.x = s.x * (1.0f - g.x) + v.x * g.x;
        p.y = s.y * (1.0f - g.y) + v.y * g.y;
        p.z = s.z * (1.0f - g.z) + v.z * g.z;
        p.w = s.w * (1.0f - g.w) + v.w * g.w;
        h.x = fmaxf(p.x, 0.0f);
        h.y = fmaxf(p.y, 0.0f);
        h.z = fmaxf(p.z, 0.0f);
        h.w = fmaxf(p.w, 0.0f);
        ph[i] = p;
        nh[i] = h;
    }
}

// ---------------------------------------------------------------------------
// Launch
// ---------------------------------------------------------------------------
extern "C" void kernel_launch(void* const* d_in, const int* in_sizes, int n_in,
                              void* d_out, int out_size) {
    const float* input = (const float*)d_in[0];
    const float* state = (const float*)d_in[1];
    const float* gw    = (const float*)d_in[2];
    const float* gb    = (const float*)d_in[3];
    const float* wi    = (const float*)d_in[4];
    float* out = (float*)d_out;

    cudaFuncSetAttribute(gemm_kernel, cudaFuncAttributeMaxDynamicSharedMemorySize,
                         GEMM_SMEM);

    // Resolve scratch symbol addresses (no allocation — just address lookup)
    __nv_bfloat16 *p_in_hi, *p_in_lo, *p_st_hi, *p_wg_hi, *p_wi_hi, *p_wi_lo;
    cudaGetSymbolAddress((void**)&p_in_hi, g_in_hi);
    cudaGetSymbolAddress((void**)&p_in_lo, g_in_lo);
    cudaGetSymbolAddress((void**)&p_st_hi, g_st_hi);
    cudaGetSymbolAddress((void**)&p_wg_hi, g_wg_hi);
    cudaGetSymbolAddress((void**)&p_wi_hi, g_wi_hi);
    cudaGetSymbolAddress((void**)&p_wi_lo, g_wi_lo);

    float4* cat = (float4*)(out + OFF_CAT);
    {
        int n4 = B_DIM * IN_DIM / 4;
        cvt_kernel<<<2048, 256>>>((const float4*)input, n4, 0, 0, cat);
    }
    {
        int n4 = B_DIM * H_DIM / 4;
        cvt_kernel<<<2048, 256>>>((const float4*)state, n4, 1, 512, cat);
    }
    {
        int n4 = H_DIM * KTOT / 4;
        cvt_kernel<<<2048, 256>>>((const float4*)gw, n4, 2, 0, nullptr);
    }
    {
        int n4 = H_DIM * IN_DIM / 4;
        cvt_kernel<<<2048, 256>>>((const float4*)wi, n4, 3, 0, nullptr);
    }

    dim3 grid((B_DIM / 128) * (H_DIM / 128));   // 1024

    // Gate GEMM: pre_gate = [in | st] @ wg^T  (2 segments, single bf16)
    gemm_kernel<<<grid, 256, GEMM_SMEM>>>(
        p_in_hi, p_st_hi, p_in_hi,
        p_wg_hi, p_wg_hi + IN_DIM, p_wg_hi,
        IN_DIM, KTOT, 2, gb, out, 0);

    // Values GEMM: in @ wi^T with hi/lo split (hh + hl + lh)
    gemm_kernel<<<grid, 256, GEMM_SMEM>>>(
        p_in_hi, p_in_hi, p_in_lo,
        p_wi_hi, p_wi_lo, p_wi_hi,
        IN_DIM, IN_DIM, 3, gb, out, 1);

    blend_kernel<<<2048, 256>>>((const float4*)state, out);
}

// round 7
// speedup vs baseline: 1.0153x; 1.0153x over previous
#include <cuda_runtime.h>
#include <cuda_bf16.h>
#include <cstdint>
#include <cstddef>

// ---------------------------------------------------------------------------
// Problem constants
// ---------------------------------------------------------------------------
#define B_DIM  8192
#define IN_DIM 2048
#define H_DIM  2048
#define KTOT   (IN_DIM + H_DIM)   // 4096

// Output layout (flattened tuple order):
//   new_h[B,H] | concat[B,4096] | pre_gate[B,H] | gate[B,H] | values[B,H] | pre_h[B,H]
static constexpr size_t OFF_NH  = 0;
static constexpr size_t OFF_CAT = (size_t)B_DIM * H_DIM;
static constexpr size_t OFF_PG  = OFF_CAT + (size_t)B_DIM * KTOT;
static constexpr size_t OFF_GT  = OFF_PG + (size_t)B_DIM * H_DIM;
static constexpr size_t OFF_VL  = OFF_GT + (size_t)B_DIM * H_DIM;
static constexpr size_t OFF_PH  = OFF_VL + (size_t)B_DIM * H_DIM;

// ---------------------------------------------------------------------------
// bf16 scratch (static device arrays — allocation-free)
// Gate GEMM uses single-rounded bf16 (bias-dominated output tolerates it).
// Values GEMM uses hi/lo split (3-term compensated product).
// ---------------------------------------------------------------------------
__device__ __align__(128) __nv_bfloat16 g_in_hi[(size_t)B_DIM * IN_DIM];
__device__ __align__(128) __nv_bfloat16 g_in_lo[(size_t)B_DIM * IN_DIM];
__device__ __align__(128) __nv_bfloat16 g_st_hi[(size_t)B_DIM * H_DIM];
__device__ __align__(128) __nv_bfloat16 g_wg_hi[(size_t)H_DIM * KTOT];
__device__ __align__(128) __nv_bfloat16 g_wi_hi[(size_t)H_DIM * IN_DIM];
__device__ __align__(128) __nv_bfloat16 g_wi_lo[(size_t)H_DIM * IN_DIM];

// ---------------------------------------------------------------------------
// Small PTX helpers (all baseline PTX — compiles for plain sm_103 target)
// ---------------------------------------------------------------------------
__device__ __forceinline__ uint32_t smem_to_u32(const void* p) {
    uint32_t a;
    asm("{ .reg .u64 t; cvta.to.shared.u64 t, %1; cvt.u32.u64 %0, t; }"
        : "=r"(a) : "l"(p));
    return a;
}

__device__ __forceinline__ void cp_async16(uint32_t dst, const void* src) {
    asm volatile("cp.async.cg.shared.global [%0], [%1], 16;\n"
                 :: "r"(dst), "l"(src));
}
#define CP_COMMIT() asm volatile("cp.async.commit_group;\n" ::: "memory")
#define CP_WAIT(n)  asm volatile("cp.async.wait_group %0;\n" :: "n"(n) : "memory")

__device__ __forceinline__ void ldsm_x4(uint32_t* r, uint32_t addr) {
    asm volatile("ldmatrix.sync.aligned.m8n8.x4.shared.b16 {%0,%1,%2,%3}, [%4];"
                 : "=r"(r[0]), "=r"(r[1]), "=r"(r[2]), "=r"(r[3]) : "r"(addr));
}

__device__ __forceinline__ void mma16816(float* c, const uint32_t* a,
                                         uint32_t b0, uint32_t b1) {
    asm volatile(
        "mma.sync.aligned.m16n8k16.row.col.f32.bf16.bf16.f32 "
        "{%0,%1,%2,%3}, {%4,%5,%6,%7}, {%8,%9}, {%0,%1,%2,%3};"
        : "+f"(c[0]), "+f"(c[1]), "+f"(c[2]), "+f"(c[3])
        : "r"(a[0]), "r"(a[1]), "r"(a[2]), "r"(a[3]), "r"(b0), "r"(b1));
}

// ---------------------------------------------------------------------------
// Pass 1: fp32 -> bf16 (hi [, lo]) split + optional concat output
// which: 0 = input (hi+lo, concat left), 1 = state (hi, concat right),
//        2 = gate_weights (hi), 3 = weights_i (hi+lo)
// ---------------------------------------------------------------------------
__global__ void cvt_kernel(const float4* __restrict__ src, int n4, int which,
                           int off4, float4* __restrict__ cdst) {
    __nv_bfloat162* hi;
    __nv_bfloat162* lo = nullptr;
    if (which == 0)      { hi = (__nv_bfloat162*)g_in_hi; lo = (__nv_bfloat162*)g_in_lo; }
    else if (which == 1) { hi = (__nv_bfloat162*)g_st_hi; }
    else if (which == 2) { hi = (__nv_bfloat162*)g_wg_hi; }
    else                 { hi = (__nv_bfloat162*)g_wi_hi; lo = (__nv_bfloat162*)g_wi_lo; }

    for (int i = blockIdx.x * blockDim.x + threadIdx.x; i < n4;
         i += gridDim.x * blockDim.x) {
        float4 v = src[i];
        __nv_bfloat16 h0 = __float2bfloat16_rn(v.x);
        __nv_bfloat16 h1 = __float2bfloat16_rn(v.y);
        __nv_bfloat16 h2 = __float2bfloat16_rn(v.z);
        __nv_bfloat16 h3 = __float2bfloat16_rn(v.w);
        __nv_bfloat162 hp0; hp0.x = h0; hp0.y = h1;
        __nv_bfloat162 hp1; hp1.x = h2; hp1.y = h3;
        hi[2 * i]     = hp0;
        hi[2 * i + 1] = hp1;
        if (lo) {
            __nv_bfloat162 lp0, lp1;
            lp0.x = __float2bfloat16_rn(v.x - __bfloat162float(h0));
            lp0.y = __float2bfloat16_rn(v.y - __bfloat162float(h1));
            lp1.x = __float2bfloat16_rn(v.z - __bfloat162float(h2));
            lp1.y = __float2bfloat16_rn(v.w - __bfloat162float(h3));
            lo[2 * i]     = lp0;
            lo[2 * i + 1] = lp1;
        }
        if (cdst) {
            int b = i >> 9;           // 512 float4 per source row
            int c = i & 511;
            cdst[(b << 10) + off4 + c] = v;
        }
    }
}

// ---------------------------------------------------------------------------
// Multi-segment bf16 TN GEMM (A [M,K] row-major, B [N,K] row-major)
//   C[M,N] = sum_seg A_seg @ B_seg^T   (fp32 accumulate via mma.sync HMMA)
// CTA tile 128x128, 256 threads, warp tile 64x32, K-chunk 32, 6-stage cp.async.
// mode 0: pre_gate/gate epilogue (add bias, clip).
// mode 1: values epilogue fused with blend (tanh, pre_h, new_h).
// ---------------------------------------------------------------------------
static constexpr int STAGES = 6;
static constexpr int STAGE_BYTES = 16384;         // A 8KB + B 8KB
static constexpr int GEMM_SMEM = STAGES * STAGE_BYTES;  // 96 KB

__device__ __forceinline__ void load_stage(uint32_t sbase, int stage,
                                           const __nv_bfloat16* A,
                                           const __nv_bfloat16* Bp,
                                           int kc, int astride, int bstride,
                                           int tid) {
    uint32_t sA = sbase + stage * STAGE_BYTES;
    uint32_t sB = sA + 8192;
#pragma unroll
    for (int h = 0; h < 2; h++) {
        int id = tid + h * 256;       // 0..511
        int r  = id >> 2;             // row 0..127
        int c4 = id & 3;              // 16B chunk within 64B row
        uint32_t sw = (uint32_t)((c4 ^ ((r >> 1) & 3)) << 4);
        cp_async16(sA + r * 64 + sw, A + (size_t)r * astride + kc + c4 * 8);
        cp_async16(sB + r * 64 + sw, Bp + (size_t)r * bstride + kc + c4 * 8);
    }
}

__global__ void __launch_bounds__(256, 2)
gemm_kernel(const __nv_bfloat16* __restrict__ a0,
            const __nv_bfloat16* __restrict__ a1,
            const __nv_bfloat16* __restrict__ a2,
            const __nv_bfloat16* __restrict__ b0,
            const __nv_bfloat16* __restrict__ b1,
            const __nv_bfloat16* __restrict__ b2,
            int astride, int bstride, int nseg,
            const float* __restrict__ bias,
            const float* __restrict__ state,
            float* __restrict__ out, int mode) {
    extern __shared__ char smem[];
    uint32_t sbase = smem_to_u32(smem);
    const int tid  = threadIdx.x;
    const int lane = tid & 31;
    const int wid  = tid >> 5;
    const int wm   = wid & 1;         // 2 warps over M
    const int wn   = wid >> 1;        // 4 warps over N

    // consecutive blocks share the M strip -> A reuse in L2
    const int nt = blockIdx.x & 15;
    const int mt = blockIdx.x >> 4;
    const int row0 = mt * 128;
    const int col0 = nt * 128;

    const __nv_bfloat16* As[3] = { a0 + (size_t)row0 * astride,
                                   a1 + (size_t)row0 * astride,
                                   a2 + (size_t)row0 * astride };
    const __nv_bfloat16* Bs[3] = { b0 + (size_t)col0 * bstride,
                                   b1 + (size_t)col0 * bstride,
                                   b2 + (size_t)col0 * bstride };

    float acc[4][4][4];               // [mfrag][n-octet][quad]
#pragma unroll
    for (int i = 0; i < 4; i++)
#pragma unroll
        for (int j = 0; j < 4; j++)
#pragma unroll
            for (int q = 0; q < 4; q++) acc[i][j][q] = 0.0f;

    const int chunks_per_seg = IN_DIM / 32;       // 64
    const int total = nseg * chunks_per_seg;

    // prologue: stages 0..STAGES-2
#pragma unroll
    for (int ci = 0; ci < STAGES - 1; ci++) {
        load_stage(sbase, ci, As[ci >> 6], Bs[ci >> 6], (ci & 63) * 32,
                   astride, bstride, tid);
        CP_COMMIT();
    }

    int ld_stage = STAGES - 1;        // next stage slot to fill
    int cp_stage = 0;                 // stage being consumed

    for (int ci = 0; ci < total; ci++) {
        CP_WAIT(STAGES - 2);
        __syncthreads();

        int nci = ci + STAGES - 1;
        if (nci < total) {
            load_stage(sbase, ld_stage, As[nci >> 6], Bs[nci >> 6],
                       (nci & 63) * 32, astride, bstride, tid);
        }
        CP_COMMIT();

        uint32_t sA = sbase + cp_stage * STAGE_BYTES;
        uint32_t sB = sA + 8192;
#pragma unroll
        for (int ks = 0; ks < 2; ks++) {
            int chunk = ks * 2 + (lane >> 4);
            uint32_t afr[4][4];
#pragma unroll
            for (int mf = 0; mf < 4; mf++) {
                int r = wm * 64 + mf * 16 + (lane & 15);
                uint32_t addr = sA + r * 64 + ((chunk ^ ((r >> 1) & 3)) << 4);
                ldsm_x4(afr[mf], addr);
            }
            uint32_t bfr[2][4];
#pragma unroll
            for (int nf = 0; nf < 2; nf++) {
                int r = wn * 32 + nf * 16 + (lane & 15);
                uint32_t addr = sB + r * 64 + ((chunk ^ ((r >> 1) & 3)) << 4);
                ldsm_x4(bfr[nf], addr);
            }
#pragma unroll
            for (int mf = 0; mf < 4; mf++)
#pragma unroll
                for (int no = 0; no < 4; no++) {
                    uint32_t bb0 = bfr[no >> 1][no & 1];
                    uint32_t bb1 = bfr[no >> 1][(no & 1) + 2];
                    mma16816(acc[mf][no], afr[mf], bb0, bb1);
                }
        }

        if (++ld_stage == STAGES) ld_stage = 0;
        if (++cp_stage == STAGES) cp_stage = 0;
    }

    // ---- Epilogue ----
    const int r_in = lane >> 2;
    const int c_in = (lane & 3) * 2;
#pragma unroll
    for (int mf = 0; mf < 4; mf++) {
#pragma unroll
        for (int no = 0; no < 4; no++) {
            int r = row0 + wm * 64 + mf * 16 + r_in;
            int c = col0 + wn * 32 + no * 8 + c_in;
            float* q = acc[mf][no];
#pragma unroll
            for (int half = 0; half < 2; half++) {
                int rr = r + half * 8;
                float d0 = q[half * 2 + 0];
                float d1 = q[half * 2 + 1];
                size_t o = (size_t)rr * H_DIM + c;
                if (mode == 0) {
                    float pg0 = d0 + bias[c];
                    float pg1 = d1 + bias[c + 1];
                    float g0 = fminf(fmaxf(pg0, 0.0f), 1.0f);
                    float g1 = fminf(fmaxf(pg1, 0.0f), 1.0f);
                    *reinterpret_cast<float2*>(out + OFF_PG + o) = make_float2(pg0, pg1);
                    *reinterpret_cast<float2*>(out + OFF_GT + o) = make_float2(g0, g1);
                } else {
                    float v0 = tanhf(d0);
                    float v1 = tanhf(d1);
                    float2 g = *reinterpret_cast<const float2*>(out + OFF_GT + o);
                    float2 s = *reinterpret_cast<const float2*>(state + o);
                    float p0 = s.x * (1.0f - g.x) + v0 * g.x;
                    float p1 = s.y * (1.0f - g.y) + v1 * g.y;
                    float h0 = fmaxf(p0, 0.0f);
                    float h1 = fmaxf(p1, 0.0f);
                    *reinterpret_cast<float2*>(out + OFF_VL + o) = make_float2(v0, v1);
                    *reinterpret_cast<float2*>(out + OFF_PH + o) = make_float2(p0, p1);
                    *reinterpret_cast<float2*>(out + OFF_NH + o) = make_float2(h0, h1);
                }
            }
        }
    }
}

// ---------------------------------------------------------------------------
// Launch
// ---------------------------------------------------------------------------
extern "C" void kernel_launch(void* const* d_in, const int* in_sizes, int n_in,
                              void* d_out, int out_size) {
    const float* input = (const float*)d_in[0];
    const float* state = (const float*)d_in[1];
    const float* gw    = (const float*)d_in[2];
    const float* gb    = (const float*)d_in[3];
    const float* wi    = (const float*)d_in[4];
    float* out = (float*)d_out;

    cudaFuncSetAttribute(gemm_kernel, cudaFuncAttributeMaxDynamicSharedMemorySize,
                         GEMM_SMEM);

    // Resolve scratch symbol addresses (no allocation — just address lookup)
    __nv_bfloat16 *p_in_hi, *p_in_lo, *p_st_hi, *p_wg_hi, *p_wi_hi, *p_wi_lo;
    cudaGetSymbolAddress((void**)&p_in_hi, g_in_hi);
    cudaGetSymbolAddress((void**)&p_in_lo, g_in_lo);
    cudaGetSymbolAddress((void**)&p_st_hi, g_st_hi);
    cudaGetSymbolAddress((void**)&p_wg_hi, g_wg_hi);
    cudaGetSymbolAddress((void**)&p_wi_hi, g_wi_hi);
    cudaGetSymbolAddress((void**)&p_wi_lo, g_wi_lo);

    float4* cat = (float4*)(out + OFF_CAT);
    {
        int n4 = B_DIM * IN_DIM / 4;
        cvt_kernel<<<2048, 256>>>((const float4*)input, n4, 0, 0, cat);
    }
    {
        int n4 = B_DIM * H_DIM / 4;
        cvt_kernel<<<2048, 256>>>((const float4*)state, n4, 1, 512, cat);
    }
    {
        int n4 = H_DIM * KTOT / 4;
        cvt_kernel<<<2048, 256>>>((const float4*)gw, n4, 2, 0, nullptr);
    }
    {
        int n4 = H_DIM * IN_DIM / 4;
        cvt_kernel<<<2048, 256>>>((const float4*)wi, n4, 3, 0, nullptr);
    }

    dim3 grid((B_DIM / 128) * (H_DIM / 128));   // 1024

    // Gate GEMM: pre_gate = [in | st] @ wg^T  (2 segments, single bf16)
    gemm_kernel<<<grid, 256, GEMM_SMEM>>>(
        p_in_hi, p_st_hi, p_in_hi,
        p_wg_hi, p_wg_hi + IN_DIM, p_wg_hi,
        IN_DIM, KTOT, 2, gb, state, out, 0);

    // Values GEMM (hi/lo split, 3 segments) + fused blend epilogue
    gemm_kernel<<<grid, 256, GEMM_SMEM>>>(
        p_in_hi, p_in_hi, p_in_lo,
        p_wi_hi, p_wi_lo, p_wi_hi,
        IN_DIM, IN_DIM, 3, gb, state, out, 1);
}

// round 9
// speedup vs baseline: 1.4987x; 1.4761x over previous
#include <cuda_runtime.h>
#include <cuda_bf16.h>
#include <cuda_fp16.h>
#include <cstdint>
#include <cstddef>

// ---------------------------------------------------------------------------
// Problem constants
// ---------------------------------------------------------------------------
#define B_DIM  8192
#define IN_DIM 2048
#define H_DIM  2048
#define KTOT   (IN_DIM + H_DIM)   // 4096

// Output layout (flattened tuple order):
//   new_h[B,H] | concat[B,4096] | pre_gate[B,H] | gate[B,H] | values[B,H] | pre_h[B,H]
static constexpr size_t OFF_NH  = 0;
static constexpr size_t OFF_CAT = (size_t)B_DIM * H_DIM;
static constexpr size_t OFF_PG  = OFF_CAT + (size_t)B_DIM * KTOT;
static constexpr size_t OFF_GT  = OFF_PG + (size_t)B_DIM * H_DIM;
static constexpr size_t OFF_VL  = OFF_GT + (size_t)B_DIM * H_DIM;
static constexpr size_t OFF_PH  = OFF_VL + (size_t)B_DIM * H_DIM;

// ---------------------------------------------------------------------------
// Scratch (static device arrays — allocation-free).
// Precision plan (calibrated round 8, per-output metric):
//  * gate GEMM: bf16 ok — pre_gate is bias-dominated (0.5 ± 0.009), measured 4e-5.
//  * values GEMM: bf16 FAILS (2.2e-3 measured) — output norm ~0.013 means matmul
//    relative rounding is the output error. fp16 (10-bit mantissa) = 4x less
//    rounding -> predicted ~5.5e-4. Single K=2048 pass.
// ---------------------------------------------------------------------------
__device__ __align__(128) __nv_bfloat16 g_in_bf[(size_t)B_DIM * IN_DIM];
__device__ __align__(128) __nv_bfloat16 g_st_bf[(size_t)B_DIM * H_DIM];
__device__ __align__(128) __nv_bfloat16 g_wg_bf[(size_t)H_DIM * KTOT];
__device__ __align__(128) __half        g_in_hf[(size_t)B_DIM * IN_DIM];
__device__ __align__(128) __half        g_wi_hf[(size_t)H_DIM * IN_DIM];

// ---------------------------------------------------------------------------
// Small PTX helpers (all baseline PTX — compiles for plain sm_103 target)
// ---------------------------------------------------------------------------
__device__ __forceinline__ uint32_t smem_to_u32(const void* p) {
    uint32_t a;
    asm("{ .reg .u64 t; cvta.to.shared.u64 t, %1; cvt.u32.u64 %0, t; }"
        : "=r"(a) : "l"(p));
    return a;
}

__device__ __forceinline__ void cp_async16(uint32_t dst, const void* src) {
    asm volatile("cp.async.cg.shared.global [%0], [%1], 16;\n"
                 :: "r"(dst), "l"(src));
}
#define CP_COMMIT() asm volatile("cp.async.commit_group;\n" ::: "memory")
#define CP_WAIT(n)  asm volatile("cp.async.wait_group %0;\n" :: "n"(n) : "memory")

__device__ __forceinline__ void ldsm_x4(uint32_t* r, uint32_t addr) {
    asm volatile("ldmatrix.sync.aligned.m8n8.x4.shared.b16 {%0,%1,%2,%3}, [%4];"
                 : "=r"(r[0]), "=r"(r[1]), "=r"(r[2]), "=r"(r[3]) : "r"(addr));
}

__device__ __forceinline__ void mma_bf16(float* c, const uint32_t* a,
                                         uint32_t b0, uint32_t b1) {
    asm volatile(
        "mma.sync.aligned.m16n8k16.row.col.f32.bf16.bf16.f32 "
        "{%0,%1,%2,%3}, {%4,%5,%6,%7}, {%8,%9}, {%0,%1,%2,%3};"
        : "+f"(c[0]), "+f"(c[1]), "+f"(c[2]), "+f"(c[3])
        : "r"(a[0]), "r"(a[1]), "r"(a[2]), "r"(a[3]), "r"(b0), "r"(b1));
}

__device__ __forceinline__ void mma_f16(float* c, const uint32_t* a,
                                        uint32_t b0, uint32_t b1) {
    asm volatile(
        "mma.sync.aligned.m16n8k16.row.col.f32.f16.f16.f32 "
        "{%0,%1,%2,%3}, {%4,%5,%6,%7}, {%8,%9}, {%0,%1,%2,%3};"
        : "+f"(c[0]), "+f"(c[1]), "+f"(c[2]), "+f"(c[3])
        : "r"(a[0]), "r"(a[1]), "r"(a[2]), "r"(a[3]), "r"(b0), "r"(b1));
}

// ---------------------------------------------------------------------------
// Pass 1: fp32 -> bf16 / fp16 + optional concat output
// which: 0 = input (bf16 + fp16 + concat left), 1 = state (bf16, concat right),
//        2 = gate_weights (bf16), 3 = weights_i (fp16)
// ---------------------------------------------------------------------------
__global__ void cvt_kernel(const float4* __restrict__ src, int n4, int which,
                           int off4, float4* __restrict__ cdst) {
    __nv_bfloat162* bf = nullptr;
    __half2* hf = nullptr;
    if (which == 0)      { bf = (__nv_bfloat162*)g_in_bf; hf = (__half2*)g_in_hf; }
    else if (which == 1) { bf = (__nv_bfloat162*)g_st_bf; }
    else if (which == 2) { bf = (__nv_bfloat162*)g_wg_bf; }
    else                 { hf = (__half2*)g_wi_hf; }

    for (int i = blockIdx.x * blockDim.x + threadIdx.x; i < n4;
         i += gridDim.x * blockDim.x) {
        float4 v = src[i];
        if (bf) {
            __nv_bfloat162 b0, b1;
            b0.x = __float2bfloat16_rn(v.x);
            b0.y = __float2bfloat16_rn(v.y);
            b1.x = __float2bfloat16_rn(v.z);
            b1.y = __float2bfloat16_rn(v.w);
            bf[2 * i]     = b0;
            bf[2 * i + 1] = b1;
        }
        if (hf) {
            __half2 h0, h1;
            h0.x = __float2half_rn(v.x);
            h0.y = __float2half_rn(v.y);
            h1.x = __float2half_rn(v.z);
            h1.y = __float2half_rn(v.w);
            hf[2 * i]     = h0;
            hf[2 * i + 1] = h1;
        }
        if (cdst) {
            int b = i >> 9;           // 512 float4 per source row
            int c = i & 511;
            cdst[(b << 10) + off4 + c] = v;
        }
    }
}

// ---------------------------------------------------------------------------
// Multi-segment 16-bit TN GEMM (A [M,K] row-major, B [N,K] row-major)
//   C[M,N] = sum_seg A_seg @ B_seg^T   (fp32 accumulate via mma.sync HMMA)
// CTA tile 128x128, 256 threads, warp tile 64x32, K-chunk 32, 6-stage cp.async.
// MODE 0: bf16, pre_gate/gate epilogue (add bias, clip).
// MODE 1: fp16, values epilogue fused with blend (tanh, pre_h, new_h).
// ---------------------------------------------------------------------------
static constexpr int STAGES = 6;
static constexpr int STAGE_BYTES = 16384;         // A 8KB + B 8KB
static constexpr int GEMM_SMEM = STAGES * STAGE_BYTES;  // 96 KB

__device__ __forceinline__ void load_stage(uint32_t sbase, int stage,
                                           const uint16_t* A,
                                           const uint16_t* Bp,
                                           int kc, int astride, int bstride,
                                           int tid) {
    uint32_t sA = sbase + stage * STAGE_BYTES;
    uint32_t sB = sA + 8192;
#pragma unroll
    for (int h = 0; h < 2; h++) {
        int id = tid + h * 256;       // 0..511
        int r  = id >> 2;             // row 0..127
        int c4 = id & 3;              // 16B chunk within 64B row
        uint32_t sw = (uint32_t)((c4 ^ ((r >> 1) & 3)) << 4);
        cp_async16(sA + r * 64 + sw, A + (size_t)r * astride + kc + c4 * 8);
        cp_async16(sB + r * 64 + sw, Bp + (size_t)r * bstride + kc + c4 * 8);
    }
}

template <int MODE>
__global__ void __launch_bounds__(256, 2)
gemm_kernel(const uint16_t* __restrict__ a0,
            const uint16_t* __restrict__ a1,
            const uint16_t* __restrict__ b0,
            const uint16_t* __restrict__ b1,
            int astride, int bstride, int nseg,
            const float* __restrict__ bias,
            const float* __restrict__ state,
            float* __restrict__ out) {
    extern __shared__ char smem[];
    uint32_t sbase = smem_to_u32(smem);
    const int tid  = threadIdx.x;
    const int lane = tid & 31;
    const int wid  = tid >> 5;
    const int wm   = wid & 1;         // 2 warps over M
    const int wn   = wid >> 1;        // 4 warps over N

    // consecutive blocks share the M strip -> A reuse in L2
    const int nt = blockIdx.x & 15;
    const int mt = blockIdx.x >> 4;
    const int row0 = mt * 128;
    const int col0 = nt * 128;

    const uint16_t* As[2] = { a0 + (size_t)row0 * astride,
                              a1 + (size_t)row0 * astride };
    const uint16_t* Bs[2] = { b0 + (size_t)col0 * bstride,
                              b1 + (size_t)col0 * bstride };

    float acc[4][4][4];               // [mfrag][n-octet][quad]
#pragma unroll
    for (int i = 0; i < 4; i++)
#pragma unroll
        for (int j = 0; j < 4; j++)
#pragma unroll
            for (int q = 0; q < 4; q++) acc[i][j][q] = 0.0f;

    const int chunks_per_seg = IN_DIM / 32;       // 64
    const int total = nseg * chunks_per_seg;

    // prologue: stages 0..STAGES-2
#pragma unroll
    for (int ci = 0; ci < STAGES - 1; ci++) {
        load_stage(sbase, ci, As[ci >> 6], Bs[ci >> 6], (ci & 63) * 32,
                   astride, bstride, tid);
        CP_COMMIT();
    }

    int ld_stage = STAGES - 1;        // next stage slot to fill
    int cp_stage = 0;                 // stage being consumed

    for (int ci = 0; ci < total; ci++) {
        CP_WAIT(STAGES - 2);
        __syncthreads();

        int nci = ci + STAGES - 1;
        if (nci < total) {
            load_stage(sbase, ld_stage, As[nci >> 6], Bs[nci >> 6],
                       (nci & 63) * 32, astride, bstride, tid);
        }
        CP_COMMIT();

        uint32_t sA = sbase + cp_stage * STAGE_BYTES;
        uint32_t sB = sA + 8192;
#pragma unroll
        for (int ks = 0; ks < 2; ks++) {
            int chunk = ks * 2 + (lane >> 4);
            uint32_t afr[4][4];
#pragma unroll
            for (int mf = 0; mf < 4; mf++) {
                int r = wm * 64 + mf * 16 + (lane & 15);
                uint32_t addr = sA + r * 64 + ((chunk ^ ((r >> 1) & 3)) << 4);
                ldsm_x4(afr[mf], addr);
            }
            uint32_t bfr[2][4];
#pragma unroll
            for (int nf = 0; nf < 2; nf++) {
                int r = wn * 32 + nf * 16 + (lane & 15);
                uint32_t addr = sB + r * 64 + ((chunk ^ ((r >> 1) & 3)) << 4);
                ldsm_x4(bfr[nf], addr);
            }
#pragma unroll
            for (int mf = 0; mf < 4; mf++)
#pragma unroll
                for (int no = 0; no < 4; no++) {
                    uint32_t bb0 = bfr[no >> 1][no & 1];
                    uint32_t bb1 = bfr[no >> 1][(no & 1) + 2];
                    if (MODE == 0)
                        mma_bf16(acc[mf][no], afr[mf], bb0, bb1);
                    else
                        mma_f16(acc[mf][no], afr[mf], bb0, bb1);
                }
        }

        if (++ld_stage == STAGES) ld_stage = 0;
        if (++cp_stage == STAGES) cp_stage = 0;
    }

    // ---- Epilogue ----
    const int r_in = lane >> 2;
    const int c_in = (lane & 3) * 2;
#pragma unroll
    for (int mf = 0; mf < 4; mf++) {
#pragma unroll
        for (int no = 0; no < 4; no++) {
            int r = row0 + wm * 64 + mf * 16 + r_in;
            int c = col0 + wn * 32 + no * 8 + c_in;
            float* q = acc[mf][no];
#pragma unroll
            for (int half = 0; half < 2; half++) {
                int rr = r + half * 8;
                float d0 = q[half * 2 + 0];
                float d1 = q[half * 2 + 1];
                size_t o = (size_t)rr * H_DIM + c;
                if (MODE == 0) {
                    float pg0 = d0 + bias[c];
                    float pg1 = d1 + bias[c + 1];
                    float g0 = fminf(fmaxf(pg0, 0.0f), 1.0f);
                    float g1 = fminf(fmaxf(pg1, 0.0f), 1.0f);
                    *reinterpret_cast<float2*>(out + OFF_PG + o) = make_float2(pg0, pg1);
                    *reinterpret_cast<float2*>(out + OFF_GT + o) = make_float2(g0, g1);
                } else {
                    float v0 = tanhf(d0);
                    float v1 = tanhf(d1);
                    float2 g = *reinterpret_cast<const float2*>(out + OFF_GT + o);
                    float2 s = *reinterpret_cast<const float2*>(state + o);
                    float p0 = s.x * (1.0f - g.x) + v0 * g.x;
                    float p1 = s.y * (1.0f - g.y) + v1 * g.y;
                    float h0 = fmaxf(p0, 0.0f);
                    float h1 = fmaxf(p1, 0.0f);
                    *reinterpret_cast<float2*>(out + OFF_VL + o) = make_float2(v0, v1);
                    *reinterpret_cast<float2*>(out + OFF_PH + o) = make_float2(p0, p1);
                    *reinterpret_cast<float2*>(out + OFF_NH + o) = make_float2(h0, h1);
                }
            }
        }
    }
}

// ---------------------------------------------------------------------------
// Launch
// ---------------------------------------------------------------------------
extern "C" void kernel_launch(void* const* d_in, const int* in_sizes, int n_in,
                              void* d_out, int out_size) {
    const float* input = (const float*)d_in[0];
    const float* state = (const float*)d_in[1];
    const float* gw    = (const float*)d_in[2];
    const float* gb    = (const float*)d_in[3];
    const float* wi    = (const float*)d_in[4];
    float* out = (float*)d_out;

    cudaFuncSetAttribute(gemm_kernel<0>, cudaFuncAttributeMaxDynamicSharedMemorySize,
                         GEMM_SMEM);
    cudaFuncSetAttribute(gemm_kernel<1>, cudaFuncAttributeMaxDynamicSharedMemorySize,
                         GEMM_SMEM);

    // Resolve scratch symbol addresses (no allocation — just address lookup)
    uint16_t *p_in_bf, *p_st_bf, *p_wg_bf, *p_in_hf, *p_wi_hf;
    cudaGetSymbolAddress((void**)&p_in_bf, g_in_bf);
    cudaGetSymbolAddress((void**)&p_st_bf, g_st_bf);
    cudaGetSymbolAddress((void**)&p_wg_bf, g_wg_bf);
    cudaGetSymbolAddress((void**)&p_in_hf, g_in_hf);
    cudaGetSymbolAddress((void**)&p_wi_hf, g_wi_hf);

    float4* cat = (float4*)(out + OFF_CAT);
    {
        int n4 = B_DIM * IN_DIM / 4;
        cvt_kernel<<<2048, 256>>>((const float4*)input, n4, 0, 0, cat);
    }
    {
        int n4 = B_DIM * H_DIM / 4;
        cvt_kernel<<<2048, 256>>>((const float4*)state, n4, 1, 512, cat);
    }
    {
        int n4 = H_DIM * KTOT / 4;
        cvt_kernel<<<2048, 256>>>((const float4*)gw, n4, 2, 0, nullptr);
    }
    {
        int n4 = H_DIM * IN_DIM / 4;
        cvt_kernel<<<2048, 256>>>((const float4*)wi, n4, 3, 0, nullptr);
    }

    dim3 grid((B_DIM / 128) * (H_DIM / 128));   // 1024

    // Gate GEMM (bf16): pre_gate = [in | st] @ wg^T  (2 segments over K)
    gemm_kernel<0><<<grid, 256, GEMM_SMEM>>>(
        p_in_bf, p_st_bf,
        p_wg_bf, p_wg_bf + IN_DIM,
        IN_DIM, KTOT, 2, gb, state, out);

    // Values GEMM (fp16, single segment) + fused blend epilogue
    gemm_kernel<1><<<grid, 256, GEMM_SMEM>>>(
        p_in_hf, p_in_hf,
        p_wi_hf, p_wi_hf,
        IN_DIM, IN_DIM, 1, gb, state, out);
}

// round 10
// speedup vs baseline: 1.6799x; 1.1209x over previous
#include <cuda_runtime.h>
#include <cuda_bf16.h>
#include <cuda_fp16.h>
#include <cstdint>
#include <cstddef>

// ---------------------------------------------------------------------------
// Problem constants
// ---------------------------------------------------------------------------
#define B_DIM  8192
#define IN_DIM 2048
#define H_DIM  2048
#define KTOT   (IN_DIM + H_DIM)   // 4096

// Output layout (flattened tuple order):
//   new_h[B,H] | concat[B,4096] | pre_gate[B,H] | gate[B,H] | values[B,H] | pre_h[B,H]
static constexpr size_t OFF_NH  = 0;
static constexpr size_t OFF_CAT = (size_t)B_DIM * H_DIM;
static constexpr size_t OFF_PG  = OFF_CAT + (size_t)B_DIM * KTOT;
static constexpr size_t OFF_GT  = OFF_PG + (size_t)B_DIM * H_DIM;
static constexpr size_t OFF_VL  = OFF_GT + (size_t)B_DIM * H_DIM;
static constexpr size_t OFF_PH  = OFF_VL + (size_t)B_DIM * H_DIM;

// ---------------------------------------------------------------------------
// Scratch (static device arrays — allocation-free).
// Precision plan (calibrated rounds 8-9, per-output metric):
//  * gate GEMM: bf16 (pre_gate bias-dominated, measured 4e-5).
//  * values GEMM: fp16 single pass (measured 2.8e-4, 3.6x margin).
// ---------------------------------------------------------------------------
__device__ __align__(128) __nv_bfloat16 g_in_bf[(size_t)B_DIM * IN_DIM];
__device__ __align__(128) __nv_bfloat16 g_st_bf[(size_t)B_DIM * H_DIM];
__device__ __align__(128) __nv_bfloat16 g_wg_bf[(size_t)H_DIM * KTOT];
__device__ __align__(128) __half        g_in_hf[(size_t)B_DIM * IN_DIM];
__device__ __align__(128) __half        g_wi_hf[(size_t)H_DIM * IN_DIM];

// ---------------------------------------------------------------------------
// Small PTX helpers (all baseline PTX — compiles for plain sm_103 target)
// ---------------------------------------------------------------------------
__device__ __forceinline__ uint32_t smem_to_u32(const void* p) {
    uint32_t a;
    asm("{ .reg .u64 t; cvta.to.shared.u64 t, %1; cvt.u32.u64 %0, t; }"
        : "=r"(a) : "l"(p));
    return a;
}

__device__ __forceinline__ void cp_async16(uint32_t dst, const void* src) {
    asm volatile("cp.async.cg.shared.global [%0], [%1], 16;\n"
                 :: "r"(dst), "l"(src));
}
#define CP_COMMIT() asm volatile("cp.async.commit_group;\n" ::: "memory")
#define CP_WAIT(n)  asm volatile("cp.async.wait_group %0;\n" :: "n"(n) : "memory")

__device__ __forceinline__ void ldsm_x4(uint32_t* r, uint32_t addr) {
    asm volatile("ldmatrix.sync.aligned.m8n8.x4.shared.b16 {%0,%1,%2,%3}, [%4];"
                 : "=r"(r[0]), "=r"(r[1]), "=r"(r[2]), "=r"(r[3]) : "r"(addr));
}

__device__ __forceinline__ void mma_bf16(float* c, const uint32_t* a,
                                         uint32_t b0, uint32_t b1) {
    asm volatile(
        "mma.sync.aligned.m16n8k16.row.col.f32.bf16.bf16.f32 "
        "{%0,%1,%2,%3}, {%4,%5,%6,%7}, {%8,%9}, {%0,%1,%2,%3};"
        : "+f"(c[0]), "+f"(c[1]), "+f"(c[2]), "+f"(c[3])
        : "r"(a[0]), "r"(a[1]), "r"(a[2]), "r"(a[3]), "r"(b0), "r"(b1));
}

__device__ __forceinline__ void mma_f16(float* c, const uint32_t* a,
                                        uint32_t b0, uint32_t b1) {
    asm volatile(
        "mma.sync.aligned.m16n8k16.row.col.f32.f16.f16.f32 "
        "{%0,%1,%2,%3}, {%4,%5,%6,%7}, {%8,%9}, {%0,%1,%2,%3};"
        : "+f"(c[0]), "+f"(c[1]), "+f"(c[2]), "+f"(c[3])
        : "r"(a[0]), "r"(a[1]), "r"(a[2]), "r"(a[3]), "r"(b0), "r"(b1));
}

// ---------------------------------------------------------------------------
// Pass 1: fp32 -> bf16 / fp16 + optional concat output
// which: 0 = input (bf16 + fp16 + concat left), 1 = state (bf16, concat right),
//        2 = gate_weights (bf16), 3 = weights_i (fp16)
// ---------------------------------------------------------------------------
__global__ void cvt_kernel(const float4* __restrict__ src, int n4, int which,
                           int off4, float4* __restrict__ cdst) {
    __nv_bfloat162* bf = nullptr;
    __half2* hf = nullptr;
    if (which == 0)      { bf = (__nv_bfloat162*)g_in_bf; hf = (__half2*)g_in_hf; }
    else if (which == 1) { bf = (__nv_bfloat162*)g_st_bf; }
    else if (which == 2) { bf = (__nv_bfloat162*)g_wg_bf; }
    else                 { hf = (__half2*)g_wi_hf; }

    for (int i = blockIdx.x * blockDim.x + threadIdx.x; i < n4;
         i += gridDim.x * blockDim.x) {
        float4 v = src[i];
        if (bf) {
            __nv_bfloat162 b0, b1;
            b0.x = __float2bfloat16_rn(v.x);
            b0.y = __float2bfloat16_rn(v.y);
            b1.x = __float2bfloat16_rn(v.z);
            b1.y = __float2bfloat16_rn(v.w);
            bf[2 * i]     = b0;
            bf[2 * i + 1] = b1;
        }
        if (hf) {
            __half2 h0, h1;
            h0.x = __float2half_rn(v.x);
            h0.y = __float2half_rn(v.y);
            h1.x = __float2half_rn(v.z);
            h1.y = __float2half_rn(v.w);
            hf[2 * i]     = h0;
            hf[2 * i + 1] = h1;
        }
        if (cdst) {
            int b = i >> 9;           // 512 float4 per source row
            int c = i & 511;
            cdst[(b << 10) + off4 + c] = v;
        }
    }
}

// ---------------------------------------------------------------------------
// Multi-segment 16-bit TN GEMM (A [M,K] row-major, B [N,K] row-major)
//   C[M,N] = sum_seg A_seg @ B_seg^T   (fp32 accumulate via mma.sync HMMA)
// CTA tile 128x128, 256 threads, warp tile 64x32.
// K-chunk 64 per iteration (4 k16 sub-steps), 3-stage cp.async, 96 KB smem.
// Stage: A 128x64 (16KB, 128B rows) + B 128x64 (16KB). 8-chunk XOR swizzle
// (c ^ (r&7)) — conflict-free for both cp.async stores and ldmatrix reads.
// MODE 0: bf16, pre_gate/gate epilogue.  MODE 1: fp16, values+blend epilogue.
// ---------------------------------------------------------------------------
static constexpr int STAGES = 3;
static constexpr int STAGE_BYTES = 32768;         // A 16KB + B 16KB
static constexpr int GEMM_SMEM = STAGES * STAGE_BYTES;  // 96 KB

__device__ __forceinline__ void load_stage(uint32_t sbase, int stage,
                                           const uint16_t* A,
                                           const uint16_t* Bp,
                                           int kc, int astride, int bstride,
                                           int tid) {
    uint32_t sA = sbase + stage * STAGE_BYTES;
    uint32_t sB = sA + 16384;
#pragma unroll
    for (int h = 0; h < 4; h++) {
        int id = tid + h * 256;       // 0..1023
        int r  = id >> 3;             // row 0..127
        int c8 = id & 7;              // 16B chunk within 128B row
        uint32_t sw = (uint32_t)((c8 ^ (r & 7)) << 4);
        cp_async16(sA + r * 128 + sw, A + (size_t)r * astride + kc + c8 * 8);
        cp_async16(sB + r * 128 + sw, Bp + (size_t)r * bstride + kc + c8 * 8);
    }
}

template <int MODE>
__global__ void __launch_bounds__(256, 2)
gemm_kernel(const uint16_t* __restrict__ a0,
            const uint16_t* __restrict__ a1,
            const uint16_t* __restrict__ b0,
            const uint16_t* __restrict__ b1,
            int astride, int bstride, int nseg,
            const float* __restrict__ bias,
            const float* __restrict__ state,
            float* __restrict__ out) {
    extern __shared__ char smem[];
    uint32_t sbase = smem_to_u32(smem);
    const int tid  = threadIdx.x;
    const int lane = tid & 31;
    const int wid  = tid >> 5;
    const int wm   = wid & 1;         // 2 warps over M
    const int wn   = wid >> 1;        // 4 warps over N

    // consecutive blocks share the M strip -> A reuse in L2
    const int nt = blockIdx.x & 15;
    const int mt = blockIdx.x >> 4;
    const int row0 = mt * 128;
    const int col0 = nt * 128;

    const uint16_t* As[2] = { a0 + (size_t)row0 * astride,
                              a1 + (size_t)row0 * astride };
    const uint16_t* Bs[2] = { b0 + (size_t)col0 * bstride,
                              b1 + (size_t)col0 * bstride };

    float acc[4][4][4];               // [mfrag][n-octet][quad]
#pragma unroll
    for (int i = 0; i < 4; i++)
#pragma unroll
        for (int j = 0; j < 4; j++)
#pragma unroll
            for (int q = 0; q < 4; q++) acc[i][j][q] = 0.0f;

    const int chunks_per_seg = IN_DIM / 64;       // 32
    const int total = nseg * chunks_per_seg;

    // prologue: stages 0..STAGES-2
#pragma unroll
    for (int ci = 0; ci < STAGES - 1; ci++) {
        load_stage(sbase, ci, As[ci >> 5], Bs[ci >> 5], (ci & 31) * 64,
                   astride, bstride, tid);
        CP_COMMIT();
    }

    int ld_stage = STAGES - 1;        // next stage slot to fill
    int cp_stage = 0;                 // stage being consumed

    for (int ci = 0; ci < total; ci++) {
        CP_WAIT(STAGES - 2);
        __syncthreads();

        int nci = ci + STAGES - 1;
        if (nci < total) {
            load_stage(sbase, ld_stage, As[nci >> 5], Bs[nci >> 5],
                       (nci & 31) * 64, astride, bstride, tid);
        }
        CP_COMMIT();

        uint32_t sA = sbase + cp_stage * STAGE_BYTES;
        uint32_t sB = sA + 16384;
#pragma unroll
        for (int ks = 0; ks < 4; ks++) {
            int chunk = ks * 2 + (lane >> 4);
            uint32_t afr[4][4];
#pragma unroll
            for (int mf = 0; mf < 4; mf++) {
                int r = wm * 64 + mf * 16 + (lane & 15);
                uint32_t addr = sA + r * 128 + ((chunk ^ (r & 7)) << 4);
                ldsm_x4(afr[mf], addr);
            }
            uint32_t bfr[2][4];
#pragma unroll
            for (int nf = 0; nf < 2; nf++) {
                int r = wn * 32 + nf * 16 + (lane & 15);
                uint32_t addr = sB + r * 128 + ((chunk ^ (r & 7)) << 4);
                ldsm_x4(bfr[nf], addr);
            }
#pragma unroll
            for (int mf = 0; mf < 4; mf++)
#pragma unroll
                for (int no = 0; no < 4; no++) {
                    uint32_t bb0 = bfr[no >> 1][no & 1];
                    uint32_t bb1 = bfr[no >> 1][(no & 1) + 2];
                    if (MODE == 0)
                        mma_bf16(acc[mf][no], afr[mf], bb0, bb1);
                    else
                        mma_f16(acc[mf][no], afr[mf], bb0, bb1);
                }
        }

        if (++ld_stage == STAGES) ld_stage = 0;
        if (++cp_stage == STAGES) cp_stage = 0;
    }

    // ---- Epilogue ----
    const int r_in = lane >> 2;
    const int c_in = (lane & 3) * 2;
#pragma unroll
    for (int mf = 0; mf < 4; mf++) {
#pragma unroll
        for (int no = 0; no < 4; no++) {
            int r = row0 + wm * 64 + mf * 16 + r_in;
            int c = col0 + wn * 32 + no * 8 + c_in;
            float* q = acc[mf][no];
#pragma unroll
            for (int half = 0; half < 2; half++) {
                int rr = r + half * 8;
                float d0 = q[half * 2 + 0];
                float d1 = q[half * 2 + 1];
                size_t o = (size_t)rr * H_DIM + c;
                if (MODE == 0) {
                    float pg0 = d0 + bias[c];
                    float pg1 = d1 + bias[c + 1];
                    float g0 = fminf(fmaxf(pg0, 0.0f), 1.0f);
                    float g1 = fminf(fmaxf(pg1, 0.0f), 1.0f);
                    *reinterpret_cast<float2*>(out + OFF_PG + o) = make_float2(pg0, pg1);
                    *reinterpret_cast<float2*>(out + OFF_GT + o) = make_float2(g0, g1);
                } else {
                    float v0 = tanhf(d0);
                    float v1 = tanhf(d1);
                    float2 g = *reinterpret_cast<const float2*>(out + OFF_GT + o);
                    float2 s = *reinterpret_cast<const float2*>(state + o);
                    float p0 = s.x * (1.0f - g.x) + v0 * g.x;
                    float p1 = s.y * (1.0f - g.y) + v1 * g.y;
                    float h0 = fmaxf(p0, 0.0f);
                    float h1 = fmaxf(p1, 0.0f);
                    *reinterpret_cast<float2*>(out + OFF_VL + o) = make_float2(v0, v1);
                    *reinterpret_cast<float2*>(out + OFF_PH + o) = make_float2(p0, p1);
                    *reinterpret_cast<float2*>(out + OFF_NH + o) = make_float2(h0, h1);
                }
            }
        }
    }
}

// ---------------------------------------------------------------------------
// Launch
// ---------------------------------------------------------------------------
extern "C" void kernel_launch(void* const* d_in, const int* in_sizes, int n_in,
                              void* d_out, int out_size) {
    const float* input = (const float*)d_in[0];
    const float* state = (const float*)d_in[1];
    const float* gw    = (const float*)d_in[2];
    const float* gb    = (const float*)d_in[3];
    const float* wi    = (const float*)d_in[4];
    float* out = (float*)d_out;

    cudaFuncSetAttribute(gemm_kernel<0>, cudaFuncAttributeMaxDynamicSharedMemorySize,
                         GEMM_SMEM);
    cudaFuncSetAttribute(gemm_kernel<1>, cudaFuncAttributeMaxDynamicSharedMemorySize,
                         GEMM_SMEM);

    // Resolve scratch symbol addresses (no allocation — just address lookup)
    uint16_t *p_in_bf, *p_st_bf, *p_wg_bf, *p_in_hf, *p_wi_hf;
    cudaGetSymbolAddress((void**)&p_in_bf, g_in_bf);
    cudaGetSymbolAddress((void**)&p_st_bf, g_st_bf);
    cudaGetSymbolAddress((void**)&p_wg_bf, g_wg_bf);
    cudaGetSymbolAddress((void**)&p_in_hf, g_in_hf);
    cudaGetSymbolAddress((void**)&p_wi_hf, g_wi_hf);

    float4* cat = (float4*)(out + OFF_CAT);
    {
        int n4 = B_DIM * IN_DIM / 4;
        cvt_kernel<<<2048, 256>>>((const float4*)input, n4, 0, 0, cat);
    }
    {
        int n4 = B_DIM * H_DIM / 4;
        cvt_kernel<<<2048, 256>>>((const float4*)state, n4, 1, 512, cat);
    }
    {
        int n4 = H_DIM * KTOT / 4;
        cvt_kernel<<<2048, 256>>>((const float4*)gw, n4, 2, 0, nullptr);
    }
    {
        int n4 = H_DIM * IN_DIM / 4;
        cvt_kernel<<<2048, 256>>>((const float4*)wi, n4, 3, 0, nullptr);
    }

    dim3 grid((B_DIM / 128) * (H_DIM / 128));   // 1024

    // Gate GEMM (bf16): pre_gate = [in | st] @ wg^T  (2 segments over K)
    gemm_kernel<0><<<grid, 256, GEMM_SMEM>>>(
        p_in_bf, p_st_bf,
        p_wg_bf, p_wg_bf + IN_DIM,
        IN_DIM, KTOT, 2, gb, state, out);

    // Values GEMM (fp16, single segment) + fused blend epilogue
    gemm_kernel<1><<<grid, 256, GEMM_SMEM>>>(
        p_in_hf, p_in_hf,
        p_wi_hf, p_wi_hf,
        IN_DIM, IN_DIM, 1, gb, state, out);
}